// round 17
// baseline (speedup 1.0000x reference)
#include <cuda_runtime.h>
#include <cuda_fp16.h>
#include <cstdint>

#define Bsz   8
#define Npts  16384
#define Spts  1024
#define Dfeat 256
#define CIN   512
#define CMID  256
#define COUT  256
#define CNT_INV (1.0f / (8.0f * 16384.0f))

// ---------------- scratch (device globals; no runtime allocation) ----------------
__device__ __align__(128) __half g_p2t[Bsz * Spts * Dfeat];           // points2^T [B,S,D] fp16
__device__ float g_w3[Bsz * Npts * 3];
__device__ int   g_i3[Bsz * Npts * 3];
__device__ __align__(128) __half g_ih[(size_t)Bsz * Dfeat * Npts];    // interp fp16; REUSED as y1 fp16
__device__ __align__(128) __half g_y0h[(size_t)Bsz * CMID * Npts];    // raw GEMM1 out fp16
__device__ __align__(128) __half g_w0h[CMID * CIN];                   // fp16 weights (hi only)
__device__ __align__(128) __half g_w1h[COUT * CMID];
__device__ float g_sum0[CMID], g_sq0[CMID], g_sum1[COUT], g_sq1[COUT];
__device__ float g_a0[CMID], g_be0[CMID], g_a1[COUT], g_be1[COUT];

// ---------------- helpers ----------------
__device__ __forceinline__ uint32_t smem_u32(const void* p) {
    uint32_t a;
    asm("{ .reg .u64 t; cvta.to.shared.u64 t, %1; cvt.u32.u64 %0, t; }" : "=r"(a) : "l"(p));
    return a;
}
#define LDSM4(R, A) \
    asm volatile("ldmatrix.sync.aligned.m8n8.x4.shared.b16 {%0,%1,%2,%3}, [%4];" \
        : "=r"((R)[0]), "=r"((R)[1]), "=r"((R)[2]), "=r"((R)[3]) : "r"(A))
#define LDSM4T(R, A) \
    asm volatile("ldmatrix.sync.aligned.m8n8.x4.trans.shared.b16 {%0,%1,%2,%3}, [%4];" \
        : "=r"((R)[0]), "=r"((R)[1]), "=r"((R)[2]), "=r"((R)[3]) : "r"(A))
#define MMA16816(C, A, B0, B1) \
    asm volatile("mma.sync.aligned.m16n8k16.row.col.f32.f16.f16.f32 " \
        "{%0,%1,%2,%3}, {%4,%5,%6,%7}, {%8,%9}, {%0,%1,%2,%3};" \
        : "+f"((C)[0]), "+f"((C)[1]), "+f"((C)[2]), "+f"((C)[3]) \
        : "r"((A)[0]), "r"((A)[1]), "r"((A)[2]), "r"((A)[3]), "r"(B0), "r"(B1))

// ---------------- transpose points2 [B,D,S] -> [B,S,D] fp16 ----------------
__global__ void transpose_p2_kernel(const float* __restrict__ p2) {
    __shared__ float t[32][33];
    int b = blockIdx.z, s0 = blockIdx.x * 32, d0 = blockIdx.y * 32;
    int tx = threadIdx.x, ty = threadIdx.y;
    const float* src = p2 + (size_t)b * Dfeat * Spts;
#pragma unroll
    for (int j = 0; j < 32; j += 8)
        t[ty + j][tx] = src[(size_t)(d0 + ty + j) * Spts + s0 + tx];
    __syncthreads();
    __half* dst = g_p2t + (size_t)b * Spts * Dfeat;
#pragma unroll
    for (int j = 0; j < 32; j += 8)
        dst[(size_t)(s0 + ty + j) * Dfeat + d0 + tx] = __float2half_rn(t[tx][ty + j]);
}

// ---------------- 3-NN + inverse-distance weights ----------------
__global__ void knn_kernel(const float* __restrict__ xyz1, const float* __restrict__ xyz2) {
    __shared__ float4 sP[Spts];    // {-2x, -2y, -2z, |x|^2}
    int b = blockIdx.y;
    int n = blockIdx.x * blockDim.x + threadIdx.x;
    const float* x2 = xyz2 + (size_t)b * 3 * Spts;
    for (int s = threadIdx.x; s < Spts; s += blockDim.x) {
        float X = x2[s], Y = x2[Spts + s], Z = x2[2 * Spts + s];
        sP[s] = make_float4(-2.f * X, -2.f * Y, -2.f * Z, X * X + Y * Y + Z * Z);
    }
    __syncthreads();
    const float* x1 = xyz1 + (size_t)b * 3 * Npts;
    float px = x1[n], py = x1[Npts + n], pz = x1[2 * Npts + n];
    float n1 = px * px + py * py + pz * pz;
    float d0 = 3.4e38f, d1 = 3.4e38f, d2 = 3.4e38f;
    int   i0 = 0, i1 = 0, i2 = 0;
#pragma unroll 8
    for (int s = 0; s < Spts; s++) {
        float4 q = sP[s];
        float d = fmaf(q.x, px, fmaf(q.y, py, fmaf(q.z, pz, q.w)));
        if (d < d2) {
            if (d < d1) {
                d2 = d1; i2 = i1;
                if (d < d0) { d1 = d0; i1 = i0; d0 = d; i0 = s; }
                else        { d1 = d;  i1 = s; }
            } else { d2 = d; i2 = s; }
        }
    }
    float r0 = 1.0f / (d0 + n1 + 1e-8f);
    float r1 = 1.0f / (d1 + n1 + 1e-8f);
    float r2 = 1.0f / (d2 + n1 + 1e-8f);
    float rs = 1.0f / (r0 + r1 + r2);
    int o = (b * Npts + n) * 3;
    g_w3[o] = r0 * rs; g_w3[o + 1] = r1 * rs; g_w3[o + 2] = r2 * rs;
    g_i3[o] = i0;      g_i3[o + 1] = i1;      g_i3[o + 2] = i2;
}

// ---------------- interpolation (fp16 gather) -> g_ih [B,D,N] fp16 ----------------
__global__ void interp_kernel() {
    __shared__ float tile[256 * 33];
    int b   = blockIdx.y;
    int n0  = blockIdx.x * 32;
    int tid = threadIdx.x, lane = tid & 31, wid = tid >> 5;
#pragma unroll
    for (int p = 0; p < 4; p++) {
        int nloc = wid * 4 + p;
        int n    = n0 + nloc;
        int base = (b * Npts + n) * 3;
        float w0 = g_w3[base], w1 = g_w3[base + 1], w2 = g_w3[base + 2];
        const __half* r0 = g_p2t + ((size_t)b * Spts + g_i3[base])     * Dfeat;
        const __half* r1 = g_p2t + ((size_t)b * Spts + g_i3[base + 1]) * Dfeat;
        const __half* r2 = g_p2t + ((size_t)b * Spts + g_i3[base + 2]) * Dfeat;
#pragma unroll
        for (int j = 0; j < 8; j++) {
            int d = lane + 32 * j;
            tile[d * 33 + nloc] = w0 * __half2float(r0[d])
                                + w1 * __half2float(r1[d])
                                + w2 * __half2float(r2[d]);
        }
    }
    __syncthreads();
    __half* outb = g_ih + (size_t)b * Dfeat * Npts;
#pragma unroll 4
    for (int e = tid; e < 256 * 32; e += 256) {
        int d = e >> 5, nl = e & 31;
        outb[(size_t)d * Npts + n0 + nl] = __float2half_rn(tile[d * 33 + nl]);
    }
}

// ---------------- weight prep (fp16 hi only) + stats zero folded in ----------------
__global__ void split_w0_kernel(const float* __restrict__ src) {
    int i = blockIdx.x * 256 + threadIdx.x;
    if (i < CMID * CIN) g_w0h[i] = __float2half_rn(src[i]);
    if (i < CMID) { g_sum0[i] = 0.f; g_sq0[i] = 0.f; g_sum1[i] = 0.f; g_sq1[i] = 0.f; }
}
__global__ void split_w1_kernel(const float* __restrict__ src) {
    int i = blockIdx.x * 256 + threadIdx.x;
    if (i < COUT * CMID) g_w1h[i] = __float2half_rn(src[i]);
}

// ---------------- stats finalize ----------------
__global__ void finalize0_kernel(const float* __restrict__ g, const float* __restrict__ be) {
    int c = threadIdx.x;
    float mean = g_sum0[c] * CNT_INV;
    float var  = g_sq0[c] * CNT_INV - mean * mean;
    float a    = g[c] * rsqrtf(var + 1e-5f);
    g_a0[c] = a; g_be0[c] = be[c] - mean * a;
}
__global__ void finalize1_kernel(const float* __restrict__ g, const float* __restrict__ be) {
    int c = threadIdx.x;
    float mean = g_sum1[c] * CNT_INV;
    float var  = g_sq1[c] * CNT_INV - mean * mean;
    float a    = g[c] * rsqrtf(var + 1e-5f);
    g_a1[c] = a; g_be1[c] = be[c] - mean * a;
}

// ---------------- fp16 HMMA GEMM (WHICH selects src/dst; fp16 output both stages) ----
// CTA tile 128M x 128N, K-chunk 32, 256 thr, 2 CTA/SM. B(c+1) register-prefetched
// before MMA(c); transform applied at store time. WHICH=1 writes y1 fp16 into g_ih
// (dead after GEMM1); stats accumulated from fp32 accs BEFORE quantization.
#define APAD 40
#define BPAD 136
template <int WHICH>
__global__ __launch_bounds__(256, 2)
void gemm_mma_kernel(const float* __restrict__ p1) {
    __shared__ __half sAh[128 * APAD];
    __shared__ __half sB[32 * BPAD];

    const int K   = WHICH ? CMID : CIN;
    const int nc  = K / 32;
    const int tid = threadIdx.x;
    const int lane = tid & 31, warp = tid >> 5;
    const int b  = blockIdx.z;
    const int m0 = blockIdx.x * 128;   // x fastest: CTAs sharing an n-panel are adjacent
    const int n0 = blockIdx.y * 128;
    const int wm = (warp >> 1) * 32;
    const int wn = (warp & 1) * 64;

    const __half* Wh = WHICH ? g_w1h : g_w0h;
    __half* dsth = WHICH ? g_ih : g_y0h;
    float* sum = WHICH ? g_sum1 : g_sum0;
    float* sq  = WHICH ? g_sq1  : g_sq0;

    float acc[2][8][4];
#pragma unroll
    for (int t = 0; t < 2; t++)
#pragma unroll
        for (int j = 0; j < 8; j++)
#pragma unroll
            for (int q = 0; q < 4; q++) acc[t][j][q] = 0.f;

    const uint32_t uAh = smem_u32(sAh);
    const uint32_t uB  = smem_u32(sB);
    const int a_row = wm + (lane & 15);
    const int a_col = (lane >> 4) * 8;
    const int b_row = (lane & 15);
    const int b_col = wn + (lane >> 4) * 8;

    // B prefetch state (raw, untransformed)
    uint4 brA[2], brB[2];
    float bnA[2], bnB[2];

    auto prefetch_b = [&](int c) {
#pragma unroll
        for (int i = 0; i < 2; i++) {
            int idx = i * 256 + tid;
            int r = idx >> 4, cc = (idx & 15) * 8;
            int k = c * 32 + r;
            size_t coloff = (size_t)n0 + cc;
            if (WHICH) {
                brA[i] = *(const uint4*)(g_y0h + ((size_t)b * CMID + k) * Npts + coloff);
                bnA[i] = g_a0[k]; bnB[i] = g_be0[k];
            } else if (k < Dfeat) {
                const float* src = p1 + ((size_t)b * Dfeat + k) * Npts + coloff;
                brA[i] = *(const uint4*)src;
                brB[i] = *(const uint4*)(src + 4);
            } else {
                brA[i] = *(const uint4*)(g_ih + ((size_t)b * Dfeat + (k - Dfeat)) * Npts + coloff);
            }
        }
    };
    auto store_b = [&](int c) {
#pragma unroll
        for (int i = 0; i < 2; i++) {
            int idx = i * 256 + tid;
            int r = idx >> 4, cc = (idx & 15) * 8;
            uint4 pk;
            if (WHICH) {
                uint4 raw = brA[i];
                float a = bnA[i], be = bnB[i];
                __half2* hp = (__half2*)&raw;
#pragma unroll
                for (int j = 0; j < 4; j++) {
                    float2 f = __half22float2(hp[j]);
                    f.x = fmaxf(fmaf(a, f.x, be), 0.f);
                    f.y = fmaxf(fmaf(a, f.y, be), 0.f);
                    hp[j] = __floats2half2_rn(f.x, f.y);
                }
                pk = raw;
            } else if (c * 32 < Dfeat) {     // chunk-uniform: fp32 points1 rows
                float4 v0 = *(float4*)&brA[i];
                float4 v1 = *(float4*)&brB[i];
                __half2 h0 = __floats2half2_rn(v0.x, v0.y);
                __half2 h1 = __floats2half2_rn(v0.z, v0.w);
                __half2 h2 = __floats2half2_rn(v1.x, v1.y);
                __half2 h3 = __floats2half2_rn(v1.z, v1.w);
                pk = make_uint4(*(uint32_t*)&h0, *(uint32_t*)&h1,
                                *(uint32_t*)&h2, *(uint32_t*)&h3);
            } else {
                pk = brA[i];
            }
            *(uint4*)&sB[r * BPAD + cc] = pk;
        }
    };

    prefetch_b(0);

    for (int c = 0; c < nc; c++) {
        int k0 = c * 32;
        __syncthreads();
        // ---- stage A ----
#pragma unroll
        for (int i = 0; i < 2; i++) {
            int idx = i * 256 + tid;
            int r = idx >> 2, q = (idx & 3) * 8;
            size_t go = (size_t)(m0 + r) * K + k0 + q;
            *(uint4*)&sAh[r * APAD + q] = *(const uint4*)(Wh + go);
        }
        store_b(c);
        __syncthreads();
        if (c + 1 < nc) prefetch_b(c + 1);
        // ---- MMA ----
#pragma unroll
        for (int ks = 0; ks < 2; ks++) {
            uint32_t ah[2][4];
#pragma unroll
            for (int t = 0; t < 2; t++) {
                uint32_t adr = uAh + (uint32_t)(((a_row + t * 16) * APAD + ks * 16 + a_col) * 2);
                LDSM4(ah[t], adr);
            }
#pragma unroll
            for (int jn = 0; jn < 4; jn++) {
                uint32_t bh[4];
                uint32_t badr = uB + (uint32_t)(((ks * 16 + b_row) * BPAD + b_col + jn * 16) * 2);
                LDSM4T(bh, badr);
                MMA16816(acc[0][jn * 2],     ah[0], bh[0], bh[1]);
                MMA16816(acc[1][jn * 2],     ah[1], bh[0], bh[1]);
                MMA16816(acc[0][jn * 2 + 1], ah[0], bh[2], bh[3]);
                MMA16816(acc[1][jn * 2 + 1], ah[1], bh[2], bh[3]);
            }
        }
    }

    // ---- epilogue: fp16 store + fused per-channel stats (fp32, pre-quantization) ----
    const int gr = lane >> 2, qc = (lane & 3) * 2;
#pragma unroll
    for (int t = 0; t < 2; t++) {
        int ch0 = m0 + wm + t * 16 + gr;          // rows ch0 and ch0+8
        float s0 = 0.f, q0 = 0.f, s1 = 0.f, q1 = 0.f;
        size_t col = (size_t)n0 + wn + qc;
#pragma unroll
        for (int j = 0; j < 8; j++) {
            float2 v = {acc[t][j][0], acc[t][j][1]};
            float2 w = {acc[t][j][2], acc[t][j][3]};
            s0 += v.x + v.y; q0 += v.x * v.x + v.y * v.y;
            s1 += w.x + w.y; q1 += w.x * w.x + w.y * w.y;
            __half* p0 = dsth + ((size_t)b * 256 + ch0) * Npts + col + j * 8;
            *(__half2*)p0 = __floats2half2_rn(v.x, v.y);
            *(__half2*)(p0 + 8 * (size_t)Npts) = __floats2half2_rn(w.x, w.y);
        }
#pragma unroll
        for (int o = 1; o < 4; o <<= 1) {
            s0 += __shfl_xor_sync(0xffffffffu, s0, o);
            q0 += __shfl_xor_sync(0xffffffffu, q0, o);
            s1 += __shfl_xor_sync(0xffffffffu, s1, o);
            q1 += __shfl_xor_sync(0xffffffffu, q1, o);
        }
        if ((lane & 3) == 0) {
            atomicAdd(sum + ch0, s0);      atomicAdd(sq + ch0, q0);
            atomicAdd(sum + ch0 + 8, s1);  atomicAdd(sq + ch0 + 8, q1);
        }
    }
}

// ---------------- final BN2 + ReLU: g_ih (y1 fp16) -> d_out fp32 ----------------
__global__ void bnrelu_kernel(float* __restrict__ out) {
    size_t i = (size_t)blockIdx.x * 256 + threadIdx.x;   // uint4 index (8 halfs)
    int c = (int)((i >> 11) & (COUT - 1));               // Npts/8 = 2048 uint4 per row
    float a = g_a1[c], be = g_be1[c];
    uint4 raw = ((const uint4*)g_ih)[i];
    __half2* hp = (__half2*)&raw;
    float4 o0, o1;
    float2 f0 = __half22float2(hp[0]), f1 = __half22float2(hp[1]);
    float2 f2 = __half22float2(hp[2]), f3 = __half22float2(hp[3]);
    o0.x = fmaxf(fmaf(a, f0.x, be), 0.f);
    o0.y = fmaxf(fmaf(a, f0.y, be), 0.f);
    o0.z = fmaxf(fmaf(a, f1.x, be), 0.f);
    o0.w = fmaxf(fmaf(a, f1.y, be), 0.f);
    o1.x = fmaxf(fmaf(a, f2.x, be), 0.f);
    o1.y = fmaxf(fmaf(a, f2.y, be), 0.f);
    o1.z = fmaxf(fmaf(a, f3.x, be), 0.f);
    o1.w = fmaxf(fmaf(a, f3.y, be), 0.f);
    float* dst = out + i * 8;
    *(float4*)dst       = o0;
    *(float4*)(dst + 4) = o1;
}

// ---------------- launch ----------------
extern "C" void kernel_launch(void* const* d_in, const int* in_sizes, int n_in,
                              void* d_out, int out_size) {
    const float* xyz1    = (const float*)d_in[0];
    const float* xyz2    = (const float*)d_in[1];
    const float* points1 = (const float*)d_in[2];
    const float* points2 = (const float*)d_in[3];
    const float* w0      = (const float*)d_in[4];
    const float* g0      = (const float*)d_in[6];
    const float* be0     = (const float*)d_in[7];
    const float* w1      = (const float*)d_in[8];
    const float* g1      = (const float*)d_in[10];
    const float* be1     = (const float*)d_in[11];
    float* out = (float*)d_out;

    split_w0_kernel<<<(CMID * CIN + 255) / 256, 256>>>(w0);     // also zeroes stats
    split_w1_kernel<<<(COUT * CMID + 255) / 256, 256>>>(w1);
    transpose_p2_kernel<<<dim3(Spts / 32, Dfeat / 32, Bsz), dim3(32, 8)>>>(points2);
    knn_kernel<<<dim3(Npts / 256, Bsz), 256>>>(xyz1, xyz2);
    interp_kernel<<<dim3(Npts / 32, Bsz), 256>>>();
    gemm_mma_kernel<0><<<dim3(2, Npts / 128, Bsz), 256>>>(points1);
    finalize0_kernel<<<1, CMID>>>(g0, be0);
    gemm_mma_kernel<1><<<dim3(2, Npts / 128, Bsz), 256>>>(points1);
    finalize1_kernel<<<1, COUT>>>(g1, be1);
    bnrelu_kernel<<<(int)(((size_t)Bsz * COUT * Npts / 8) / 256), 256>>>(out);
}